// round 8
// baseline (speedup 1.0000x reference)
#include <cuda_runtime.h>

// Problem constants
#define B_  2
#define E_  16
#define H_  160
#define W_  288
#define N_  12
#define T_  2
#define HW_ (H_ * W_)           // 46080
#define P_  (T_ * HW_)          // 92160 pixels per instance
#define BN_ (B_ * N_)           // 24 instances
#define NE_ (N_ * E_)           // 192
#define NBINS 16384             // error bins over [0, 2]
#define BIN_SCALE 8192.0f       // NBINS / 2
#define DBINF (2.0f / 16384.0f)
#define NSLOT (BN_ * 2)         // slot = inst*2 + mv
#define BPT 16                  // bins per thread in k_loss (NBINS/1024)
#define CPIX 384                // pixels per stats block (= 32 lanes * 12)
#define SCH (P_ / CPIX)         // 240 chunks per batch

// Scratch (static __device__ arrays — zero-initialized at load; k_loss's last
// block restores the zero state every call, so no clear kernel is needed).
__device__ unsigned int d_hist[NSLOT * NBINS];      // 3.1 MB
__device__ unsigned int d_pack[B_ * P_];            // packed masks, 737 KB
__device__ float        d_S1[BN_ * E_];
__device__ float        d_S2[BN_ * E_];
__device__ unsigned int d_cnt[BN_];
__device__ float        d_mean[BN_ * E_];
__device__ float        d_nhv [BN_ * E_];           // -0.5 * var
__device__ double       d_total;
__device__ unsigned int d_tick1;
__device__ unsigned int d_tick2;

// ---------------------------------------------------------------------------
// Kernel 1: pack masks + masked sums + (fused) finalize of mean/var.
// grid (240, B_), block 512 (warp w = embed dim e).  CPIX=384 divides HW_,
// so each chunk lies in one frame t.  All loops fully unrolled -> batched
// LDGs (high MLP); feature loads issued before the pack phase to overlap.
// ---------------------------------------------------------------------------
__global__ void __launch_bounds__(512, 2) k_stats(const float* __restrict__ mf1,
                                                  const float* __restrict__ mf2,
                                                  const int*   __restrict__ gt) {
    __shared__ unsigned int spack[CPIX];
    const int b    = blockIdx.y;
    const int tid  = threadIdx.x;
    const int p0   = blockIdx.x * CPIX;
    const int t    = p0 / HW_;
    const int hw0  = p0 - t * HW_;
    const int e    = tid >> 5;
    const int lane = tid & 31;

    // Phase A: batched feature loads (independent of pack phase)
    const float* f = (t == 0 ? mf1 : mf2) + ((size_t)b * E_ + e) * HW_ + hw0;
    float xv[12];
#pragma unroll
    for (int i = 0; i < 12; i++) xv[i] = f[lane + 32 * i];

    // Phase B: pack 12 masks/pixel into one uint32 (threads 0..383)
    if (tid < CPIX) {
        const int* g0 = gt + (((size_t)b * N_) * T_ + t) * HW_ + hw0 + tid;
        unsigned w = 0u;
#pragma unroll
        for (int n = 0; n < N_; n++)
            w |= ((unsigned)g0[n * (T_ * HW_)]) << n;
        spack[tid] = w;
        d_pack[(size_t)b * P_ + p0 + tid] = w;
    }
    __syncthreads();

    // Phase C: accumulate (s1,s2) pairs with predicated packed-f32 adds
    unsigned long long s12[N_];
#pragma unroll
    for (int n = 0; n < N_; n++) s12[n] = 0ull;

#pragma unroll
    for (int i = 0; i < 12; i++) {
        float x  = xv[i];
        float x2 = x * x;
        unsigned long long x12;
        asm("mov.b64 %0, {%1, %2};"
            : "=l"(x12) : "r"(__float_as_uint(x)), "r"(__float_as_uint(x2)));
        unsigned pw = spack[lane + 32 * i];
#pragma unroll
        for (int n = 0; n < N_; n++) {
            asm("{ .reg .pred p; setp.ne.u32 p, %1, 0;\n\t"
                "@p add.rn.f32x2 %0, %0, %2; }"
                : "+l"(s12[n]) : "r"(pw & (1u << n)), "l"(x12));
        }
    }

#pragma unroll
    for (int n = 0; n < N_; n++) {
        unsigned u1, u2;
        asm("mov.b64 {%0, %1}, %2;" : "=r"(u1), "=r"(u2) : "l"(s12[n]));
        float a  = __uint_as_float(u1);
        float bb = __uint_as_float(u2);
        for (int off = 16; off; off >>= 1) {
            a  += __shfl_down_sync(0xffffffffu, a,  off);
            bb += __shfl_down_sync(0xffffffffu, bb, off);
        }
        if (lane == 0) {
            atomicAdd(&d_S1[((size_t)b * N_ + n) * E_ + e], a);
            atomicAdd(&d_S2[((size_t)b * N_ + n) * E_ + e], bb);
        }
    }

    // counts: warp 0 only (re-reads spack from smem, cheap)
    if (e == 0) {
        int c[N_];
#pragma unroll
        for (int n = 0; n < N_; n++) c[n] = 0;
#pragma unroll
        for (int i = 0; i < 12; i++) {
            unsigned pw = spack[lane + 32 * i];
#pragma unroll
            for (int n = 0; n < N_; n++) c[n] += (int)((pw >> n) & 1u);
        }
#pragma unroll
        for (int n = 0; n < N_; n++) {
            int cc = c[n];
            for (int off = 16; off; off >>= 1)
                cc += __shfl_down_sync(0xffffffffu, cc, off);
            if (lane == 0) atomicAdd(&d_cnt[b * N_ + n], (unsigned)cc);
        }
    }

    // Fused finalize (last block)
    __threadfence();
    __shared__ bool isLast;
    if (tid == 0) isLast = (atomicAdd(&d_tick1, 1u) == (unsigned)(SCH * B_ - 1));
    __syncthreads();
    if (isLast && tid < BN_ * E_) {
        int inst   = tid / E_;
        double cnt = (double)d_cnt[inst];
        double s1v = (double)d_S1[tid];
        double s2v = (double)d_S2[tid];
        double mean = s1v / cnt;
        double var  = (s2v - s1v * s1v / cnt) / (cnt - 1.0);
        d_mean[tid] = (float)mean;
        d_nhv[tid]  = (float)(-0.5 * var);
    }
}

// ---------------------------------------------------------------------------
// Kernel 2: per-pixel distance -> error -> histogram.
// 4 pixels per thread (float4/uint4 loads), warp-aggregated atomics.
// grid 360, block 128.  Fast path: for d < -9.71, e^d < 6.05e-5 => bin is
// exactly 0 (mv=0) or NBINS-1 (mv=1) at this quantization; skip the exp.
// ---------------------------------------------------------------------------
__global__ void __launch_bounds__(128) k_hist(const float* __restrict__ mf1,
                                              const float* __restrict__ mf2) {
    __shared__ float sm_mean[NE_];
    __shared__ float sm_nhv [NE_];
    const int tid = threadIdx.x;
    const int q   = blockIdx.x * 128 + tid;          // 4-pixel group, < B_*P_/4
    const int b   = q / (P_ / 4);                    // uniform per block
    for (int i = tid; i < NE_; i += 128) {
        sm_mean[i] = d_mean[b * NE_ + i];
        sm_nhv [i] = d_nhv [b * NE_ + i];
    }
    __syncthreads();

    const int pg   = q - b * (P_ / 4);
    const int t    = pg / (HW_ / 4);
    const int hw4  = pg - t * (HW_ / 4);
    const int lane = tid & 31;

    const float* f = (t == 0 ? mf1 : mf2) + (size_t)b * E_ * HW_ + (size_t)hw4 * 4;
    float4 x[E_];
#pragma unroll
    for (int e = 0; e < E_; e++)
        x[e] = *reinterpret_cast<const float4*>(f + (size_t)e * HW_);

    const uint4 pv = reinterpret_cast<const uint4*>(d_pack)[q];
    unsigned pw[4] = {pv.x, pv.y, pv.z, pv.w};

#pragma unroll
    for (int n = 0; n < N_; n++) {
        float d0 = 0.f, d1 = 0.f, d2 = 0.f, d3 = 0.f;
#pragma unroll
        for (int e = 0; e < E_; e++) {
            const float mm = sm_mean[n * E_ + e];
            const float vv = sm_nhv [n * E_ + e];
            float a;
            a = x[e].x - mm; d0 = fmaf(a * a, vv, d0);
            a = x[e].y - mm; d1 = fmaf(a * a, vv, d1);
            a = x[e].z - mm; d2 = fmaf(a * a, vv, d2);
            a = x[e].w - mm; d3 = fmaf(a * a, vv, d3);
        }
        const float dd[4] = {d0, d1, d2, d3};
        const int slotbase = (b * N_ + n) << 1;
#pragma unroll
        for (int j = 0; j < 4; j++) {
            const unsigned mv = (pw[j] >> n) & 1u;
            int bin;
            if (dd[j] > -9.71f) {
                float qe  = __expf(dd[j]);               // in (0, 1]
                float err = mv ? fmaf(-2.0f, qe, 2.0f) : (2.0f * qe);
                bin = (int)(err * BIN_SCALE);
                bin = bin < (NBINS - 1) ? bin : (NBINS - 1);
            } else {
                bin = mv ? (NBINS - 1) : 0;              // exact at this quantization
            }
            unsigned key   = (mv << 14) | (unsigned)bin;
            unsigned peers = __match_any_sync(0xffffffffu, key);
            if (lane == __ffs(peers) - 1) {
                atomicAdd(&d_hist[(size_t)(slotbase | (int)mv) * NBINS + bin],
                          (unsigned)__popc(peers));
            }
        }
    }
}

// ---------------------------------------------------------------------------
// Kernel 3: histogram scan + Lovasz via exact int64 rational + fp32 divide.
// One block per instance; 1024 threads x 16 bins.  Also zeroes the histogram
// bins it read and (last block) resets all accumulators + writes the output.
// ---------------------------------------------------------------------------
__global__ void __launch_bounds__(1024) k_loss(float* __restrict__ out) {
    const int inst = blockIdx.x;
    const int tid  = threadIdx.x;
    const int lane = tid & 31;
    const int wid  = tid >> 5;
    const size_t baseN = ((size_t)(inst * 2)     * NBINS) + (size_t)tid * BPT;
    const size_t baseP = ((size_t)(inst * 2 + 1) * NBINS) + (size_t)tid * BPT;

    unsigned cntP[BPT], cntN[BPT];
    const uint4 z4 = make_uint4(0u, 0u, 0u, 0u);
#pragma unroll
    for (int j = 0; j < BPT; j += 4) {
        uint4 vp = *reinterpret_cast<const uint4*>(&d_hist[baseP + j]);
        uint4 vn = *reinterpret_cast<const uint4*>(&d_hist[baseN + j]);
        cntP[j] = vp.x; cntP[j+1] = vp.y; cntP[j+2] = vp.z; cntP[j+3] = vp.w;
        cntN[j] = vn.x; cntN[j+1] = vn.y; cntN[j+2] = vn.z; cntN[j+3] = vn.w;
        *reinterpret_cast<uint4*>(&d_hist[baseP + j]) = z4;   // self-clean
        *reinterpret_cast<uint4*>(&d_hist[baseN + j]) = z4;
    }
    unsigned tp = 0, tn = 0;
#pragma unroll
    for (int j = 0; j < BPT; j++) { tp += cntP[j]; tn += cntN[j]; }

    // block-wide exclusive scan: warp shuffle scan + cross-warp scan
    __shared__ unsigned swp[32], swn[32];
    unsigned ip = tp, inn = tn;
#pragma unroll
    for (int o = 1; o < 32; o <<= 1) {
        unsigned a = __shfl_up_sync(0xffffffffu, ip,  o);
        unsigned c = __shfl_up_sync(0xffffffffu, inn, o);
        if (lane >= o) { ip += a; inn += c; }
    }
    if (lane == 31) { swp[wid] = ip; swn[wid] = inn; }
    __syncthreads();
    if (wid == 0) {
        unsigned op = swp[lane], on = swn[lane];
        unsigned a = op, c = on;
#pragma unroll
        for (int o = 1; o < 32; o <<= 1) {
            unsigned xa = __shfl_up_sync(0xffffffffu, a, o);
            unsigned xc = __shfl_up_sync(0xffffffffu, c, o);
            if (lane >= o) { a += xa; c += xc; }
        }
        swp[lane] = a - op;          // exclusive warp-total prefix
        swn[lane] = c - on;
    }
    __syncthreads();
    const unsigned runP0 = swp[wid] + (ip - tp);
    const unsigned runN0 = swn[wid] + (inn - tn);

    const long long gts    = (long long)d_cnt[inst];
    const long long totNeg = (long long)P_ - gts;
    long long cp1 = gts    - (long long)runP0;
    long long cn1 = totNeg - (long long)runN0;

    float acc = 0.f;
#pragma unroll
    for (int j = 0; j < BPT; j++) {
        const unsigned cp = cntP[j], cn = cntN[j];
        if (cp | cn) {
            long long num = gts * (long long)(cp + cn)
                          + (long long)cp * cn1 - cp1 * (long long)cn;
            long long den = (gts + cn1 - (long long)cn) * (gts + cn1);
            float e_rep = ((float)(tid * BPT + j) + 0.5f) * DBINF;
            acc += e_rep * ((float)num / (float)den);
        }
        cp1 -= (long long)cp;
        cn1 -= (long long)cn;
    }

    // block reduce (double)
    __shared__ double dw[32];
    double dacc = (double)acc;
#pragma unroll
    for (int o = 16; o; o >>= 1)
        dacc += __shfl_down_sync(0xffffffffu, dacc, o);
    if (lane == 0) dw[wid] = dacc;
    __syncthreads();
    if (wid == 0) {
        double v = dw[lane];
#pragma unroll
        for (int o = 16; o; o >>= 1)
            v += __shfl_down_sync(0xffffffffu, v, o);
        if (lane == 0) atomicAdd(&d_total, v);
    }

    // last block: write scalar output, then reset all state to zero
    __threadfence();
    __shared__ bool isLast;
    if (tid == 0) isLast = (atomicAdd(&d_tick2, 1u) == (unsigned)(BN_ - 1));
    __syncthreads();
    if (isLast) {
        if (tid == 0) {
            out[0] = (float)(d_total / (double)BN_);
            d_total = 0.0;
            d_tick1 = 0u;
            d_tick2 = 0u;
        }
        if (tid < BN_ * E_) { d_S1[tid] = 0.f; d_S2[tid] = 0.f; }
        if (tid < BN_)      { d_cnt[tid] = 0u; }
    }
}

extern "C" void kernel_launch(void* const* d_in, const int* in_sizes, int n_in,
                              void* d_out, int out_size) {
    const float* mf1 = (const float*)d_in[0];
    const float* mf2 = (const float*)d_in[1];
    const int*   gt  = (const int*)d_in[2];

    k_stats<<<dim3(SCH, B_), 512>>>(mf1, mf2, gt);
    k_hist<<<(B_ * P_) / (128 * 4), 128>>>(mf1, mf2);
    k_loss<<<BN_, 1024>>>((float*)d_out);
}

// round 9
// speedup vs baseline: 1.0692x; 1.0692x over previous
#include <cuda_runtime.h>

// Problem constants
#define B_  2
#define E_  16
#define H_  160
#define W_  288
#define N_  12
#define T_  2
#define HW_ (H_ * W_)           // 46080
#define P_  (T_ * HW_)          // 92160 pixels per instance
#define BN_ (B_ * N_)           // 24 instances
#define NE_ (N_ * E_)           // 192
#define NBINS 16384             // error bins over [0, 2]
#define BIN_SCALE 8192.0f       // NBINS / 2
#define DBINF (2.0f / 16384.0f)
#define NSLOT (BN_ * 2)         // slot = inst*2 + mv
#define PPB 640                 // pixels per block (divides HW_)
#define NBLK (B_ * P_ / PPB)    // 288 blocks, all resident (2/SM on 148 SMs)
#define BPT2 32                 // bins per thread in loss phase (NBINS/512)

// Scratch (static __device__ arrays — zero-initialized at load; the final
// block restores the zero state every call, so no clear kernel is needed).
__device__ unsigned int d_hist[NSLOT * NBINS];      // 3.1 MB
__device__ float        d_S1[BN_ * E_];
__device__ float        d_S2[BN_ * E_];
__device__ unsigned int d_cnt[BN_];
__device__ float        d_mean[BN_ * E_];
__device__ float        d_nhv [BN_ * E_];           // -0.5 * var
__device__ double       d_total;
__device__ unsigned int d_tick1;
__device__ unsigned int d_tick2;
__device__ unsigned int d_tick3;
__device__ unsigned int d_flag1;

// ---------------------------------------------------------------------------
// Single persistent kernel.  All 288 blocks are resident, so cross-block
// spin-wait barriers are safe.
//   Phase 1: pack masks (smem) + masked sums; last block finalizes mean/var.
//   Phase 2: per-pixel distance -> error -> histogram (warp-agg atomics).
//   Phase 3: blocks 0..23 do the Lovasz scan; last writes output + resets.
// ---------------------------------------------------------------------------
__global__ void __launch_bounds__(512, 2)
k_fused(const float* __restrict__ mf1, const float* __restrict__ mf2,
        const int* __restrict__ gt, float* __restrict__ out) {
    __shared__ unsigned int spack[PPB];
    __shared__ float sm_mean[NE_];
    __shared__ float sm_nhv [NE_];
    __shared__ unsigned int sticket;

    const int blk  = blockIdx.x;
    const int tid  = threadIdx.x;
    const int e    = tid >> 5;
    const int lane = tid & 31;

    const int base = blk * PPB;            // global pixel index in [0, B_*P_)
    const int b    = base / P_;
    const int p0   = base - b * P_;
    const int t    = p0 / HW_;             // PPB divides HW_: one frame/block
    const int hw0  = p0 - t * HW_;

    const float* fb = (t == 0 ? mf1 : mf2) + (size_t)b * E_ * HW_ + hw0;

    // ---- Phase 1a: pack 12 masks/pixel into one uint32 (smem only) ----
    const int* g0 = gt + (((size_t)b * N_) * T_ + t) * HW_ + hw0;
    for (int k = tid; k < PPB; k += 512) {
        unsigned w = 0u;
#pragma unroll
        for (int n = 0; n < N_; n++)
            w |= ((unsigned)g0[(size_t)n * (T_ * HW_) + k]) << n;
        spack[k] = w;
    }
    __syncthreads();

    // ---- Phase 1b: masked sums (warp e = embed dim e; 20 px per lane) ----
    {
        const float* f = fb + (size_t)e * HW_;
        float s1[N_], s2[N_];
#pragma unroll
        for (int n = 0; n < N_; n++) { s1[n] = 0.f; s2[n] = 0.f; }
#pragma unroll
        for (int k = 0; k < PPB / 32; k++) {
            float x  = f[lane + 32 * k];
            float x2 = x * x;
            unsigned pw = spack[lane + 32 * k];
#pragma unroll
            for (int n = 0; n < N_; n++) {
                if ((pw >> n) & 1u) { s1[n] += x; s2[n] += x2; }
            }
        }
#pragma unroll
        for (int n = 0; n < N_; n++) {
            float a  = s1[n];
            float bb = s2[n];
            for (int off = 16; off; off >>= 1) {
                a  += __shfl_down_sync(0xffffffffu, a,  off);
                bb += __shfl_down_sync(0xffffffffu, bb, off);
            }
            if (lane == 0) {
                atomicAdd(&d_S1[((size_t)b * N_ + n) * E_ + e], a);
                atomicAdd(&d_S2[((size_t)b * N_ + n) * E_ + e], bb);
            }
        }
        if (e == 0) {           // warp 0 sees all PPB pixels -> counts
            int c[N_];
#pragma unroll
            for (int n = 0; n < N_; n++) c[n] = 0;
#pragma unroll
            for (int k = 0; k < PPB / 32; k++) {
                unsigned pw = spack[lane + 32 * k];
#pragma unroll
                for (int n = 0; n < N_; n++) c[n] += (int)((pw >> n) & 1u);
            }
#pragma unroll
            for (int n = 0; n < N_; n++) {
                int cc = c[n];
                for (int off = 16; off; off >>= 1)
                    cc += __shfl_down_sync(0xffffffffu, cc, off);
                if (lane == 0) atomicAdd(&d_cnt[b * N_ + n], (unsigned)cc);
            }
        }
    }

    // ---- Barrier 1: ticket; last block finalizes mean/var, sets flag ----
    __threadfence();
    if (tid == 0) sticket = atomicAdd(&d_tick1, 1u);
    __syncthreads();
    if (sticket == (unsigned)(NBLK - 1)) {
        if (tid < BN_ * E_) {
            int inst   = tid / E_;
            float cnt  = (float)d_cnt[inst];
            float s1v  = d_S1[tid];
            float s2v  = d_S2[tid];
            float mean = s1v / cnt;
            float var  = (s2v - s1v * s1v / cnt) / (cnt - 1.0f);
            d_mean[tid] = mean;
            d_nhv[tid]  = -0.5f * var;
        }
        __syncthreads();
        __threadfence();
        if (tid == 0) atomicExch(&d_flag1, 1u);
    }
    if (tid == 0) { while (*(volatile unsigned*)&d_flag1 == 0u) {} }
    __syncthreads();
    __threadfence();

    // ---- Phase 2: histogram (feature reloads hit this SM's L1) ----
    for (int i = tid; i < NE_; i += 512) {
        sm_mean[i] = d_mean[b * NE_ + i];
        sm_nhv [i] = d_nhv [b * NE_ + i];
    }
    __syncthreads();

    for (int k = tid; k < PPB; k += 512) {
        float x[E_];
#pragma unroll
        for (int ee = 0; ee < E_; ee++) x[ee] = fb[(size_t)ee * HW_ + k];
        const unsigned pw = spack[k];
#pragma unroll
        for (int n = 0; n < N_; n++) {
            float d = 0.f;
#pragma unroll
            for (int ee = 0; ee < E_; ee++) {
                float diff = x[ee] - sm_mean[n * E_ + ee];
                d = fmaf(diff * diff, sm_nhv[n * E_ + ee], d);
            }
            float q   = __expf(d);                   // in (0, 1]
            unsigned mv = (pw >> n) & 1u;
            float err = mv ? fmaf(-2.0f, q, 2.0f) : (2.0f * q);
            int bin   = (int)(err * BIN_SCALE);
            bin       = bin < (NBINS - 1) ? bin : (NBINS - 1);

            unsigned key   = (mv << 14) | (unsigned)bin;
            unsigned peers = __match_any_sync(0xffffffffu, key);
            if (lane == (__ffs(peers) - 1)) {
                int slot = ((b * N_ + n) << 1) | (int)mv;
                atomicAdd(&d_hist[(size_t)slot * NBINS + bin],
                          (unsigned)__popc(peers));
            }
        }
    }

    // ---- Barrier 2: arrive; blocks >= BN_ are done ----
    __threadfence();
    if (tid == 0) atomicAdd(&d_tick2, 1u);
    if (blk >= BN_) return;
    if (tid == 0) { while (*(volatile unsigned*)&d_tick2 < (unsigned)NBLK) {} }
    __syncthreads();
    __threadfence();

    // ---- Phase 3: Lovasz via exact int64 rational + fp32 divide ----
    // Two passes over this thread's 32 bins to keep registers <= 64.
    const int inst = blk;
    const int wid  = tid >> 5;
    const size_t baseN = ((size_t)(inst * 2)     * NBINS) + (size_t)tid * BPT2;
    const size_t baseP = ((size_t)(inst * 2 + 1) * NBINS) + (size_t)tid * BPT2;

    unsigned tp = 0, tn = 0;
#pragma unroll
    for (int j = 0; j < BPT2; j += 4) {
        uint4 vp = *reinterpret_cast<const uint4*>(&d_hist[baseP + j]);
        uint4 vn = *reinterpret_cast<const uint4*>(&d_hist[baseN + j]);
        tp += vp.x + vp.y + vp.z + vp.w;
        tn += vn.x + vn.y + vn.z + vn.w;
    }

    // block-wide exclusive scan (512 threads): warp scan + 16 warp totals
    __shared__ unsigned swp[16], swn[16];
    unsigned ip = tp, inn = tn;
#pragma unroll
    for (int o = 1; o < 32; o <<= 1) {
        unsigned a = __shfl_up_sync(0xffffffffu, ip,  o);
        unsigned c = __shfl_up_sync(0xffffffffu, inn, o);
        if (lane >= o) { ip += a; inn += c; }
    }
    if (lane == 31) { swp[wid] = ip; swn[wid] = inn; }
    __syncthreads();
    if (wid == 0) {
        unsigned a = (lane < 16) ? swp[lane] : 0u;
        unsigned c = (lane < 16) ? swn[lane] : 0u;
        unsigned oa = a, oc = c;
#pragma unroll
        for (int o = 1; o < 32; o <<= 1) {
            unsigned xa = __shfl_up_sync(0xffffffffu, a, o);
            unsigned xc = __shfl_up_sync(0xffffffffu, c, o);
            if (lane >= o) { a += xa; c += xc; }
        }
        if (lane < 16) { swp[lane] = a - oa; swn[lane] = c - oc; }
    }
    __syncthreads();
    const unsigned runP0 = swp[wid] + (ip - tp);
    const unsigned runN0 = swn[wid] + (inn - tn);

    const long long gts    = (long long)d_cnt[inst];
    const long long totNeg = (long long)P_ - gts;
    long long cp1 = gts    - (long long)runP0;
    long long cn1 = totNeg - (long long)runN0;

    float acc = 0.f;
    const uint4 z4 = make_uint4(0u, 0u, 0u, 0u);
#pragma unroll
    for (int j4 = 0; j4 < BPT2; j4 += 4) {
        uint4 vp = *reinterpret_cast<const uint4*>(&d_hist[baseP + j4]);
        uint4 vn = *reinterpret_cast<const uint4*>(&d_hist[baseN + j4]);
        *reinterpret_cast<uint4*>(&d_hist[baseP + j4]) = z4;   // self-clean
        *reinterpret_cast<uint4*>(&d_hist[baseN + j4]) = z4;
        unsigned cpv[4] = {vp.x, vp.y, vp.z, vp.w};
        unsigned cnv[4] = {vn.x, vn.y, vn.z, vn.w};
#pragma unroll
        for (int j = 0; j < 4; j++) {
            const unsigned cp = cpv[j], cn = cnv[j];
            if (cp | cn) {
                long long num = gts * (long long)(cp + cn)
                              + (long long)cp * cn1 - cp1 * (long long)cn;
                long long den = (gts + cn1 - (long long)cn) * (gts + cn1);
                float e_rep = ((float)(tid * BPT2 + j4 + j) + 0.5f) * DBINF;
                acc += e_rep * ((float)num / (float)den);
            }
            cp1 -= (long long)cp;
            cn1 -= (long long)cn;
        }
    }

    // block reduce (double)
    __shared__ double dw[16];
    double dacc = (double)acc;
#pragma unroll
    for (int o = 16; o; o >>= 1)
        dacc += __shfl_down_sync(0xffffffffu, dacc, o);
    if (lane == 0) dw[wid] = dacc;
    __syncthreads();
    if (wid == 0) {
        double v = (lane < 16) ? dw[lane] : 0.0;
#pragma unroll
        for (int o = 8; o; o >>= 1)
            v += __shfl_down_sync(0xffffffffu, v, o);
        if (lane == 0) atomicAdd(&d_total, v);
    }

    // ---- Final: last of the 24 loss blocks writes output + resets state ----
    __threadfence();
    if (tid == 0) sticket = atomicAdd(&d_tick3, 1u);
    __syncthreads();
    if (sticket == (unsigned)(BN_ - 1)) {
        if (tid == 0) {
            out[0] = (float)(d_total / (double)BN_);
            d_total = 0.0;
            d_tick1 = 0u;
            d_tick2 = 0u;
            d_tick3 = 0u;
            d_flag1 = 0u;
        }
        if (tid < BN_ * E_) { d_S1[tid] = 0.f; d_S2[tid] = 0.f; }
        if (tid < BN_)      { d_cnt[tid] = 0u; }
    }
}

extern "C" void kernel_launch(void* const* d_in, const int* in_sizes, int n_in,
                              void* d_out, int out_size) {
    const float* mf1 = (const float*)d_in[0];
    const float* mf2 = (const float*)d_in[1];
    const int*   gt  = (const int*)d_in[2];

    k_fused<<<NBLK, 512>>>(mf1, mf2, gt, (float*)d_out);
}

// round 10
// speedup vs baseline: 1.4034x; 1.3126x over previous
#include <cuda_runtime.h>

// Problem constants
#define B_  2
#define E_  16
#define H_  160
#define W_  288
#define N_  12
#define T_  2
#define HW_ (H_ * W_)           // 46080
#define P_  (T_ * HW_)          // 92160 pixels per instance
#define BN_ (B_ * N_)           // 24 instances
#define NE_ (N_ * E_)           // 192
#define NBINS 16384             // error bins over [0, 2]
#define BIN_SCALE 8192.0f       // NBINS / 2
#define DBINF (2.0f / 16384.0f)
#define NSLOT (BN_ * 2)         // slot = inst*2 + mv
#define BPT 16                  // bins per thread in k_loss (NBINS/1024)

// Scratch (static __device__ arrays — zero-initialized at load; k_loss's last
// block restores the zero state every call, so no clear kernel is needed).
__device__ unsigned int d_hist[NSLOT * NBINS];      // 3.1 MB
__device__ unsigned int d_pack[B_ * P_];            // packed masks, 737 KB
__device__ float        d_S1[BN_ * E_];
__device__ float        d_S2[BN_ * E_];
__device__ unsigned int d_cnt[BN_];
__device__ float        d_mean[BN_ * E_];
__device__ float        d_nhv [BN_ * E_];           // -0.5 * var
__device__ double       d_total;
__device__ unsigned int d_tick1;
__device__ unsigned int d_tick2;

// ---------------------------------------------------------------------------
// Kernel 1: pack masks + masked sums + (fused) finalize of mean/var.
// grid (64 chunks, B_), block 512.  Chunk of 1440 pixels lies in one frame t.
// (R5 body; only the S1/S2 atomics are float now — proven rel_err-neutral.)
// ---------------------------------------------------------------------------
__global__ void __launch_bounds__(512) k_stats(const float* __restrict__ mf1,
                                               const float* __restrict__ mf2,
                                               const int*   __restrict__ gt) {
    __shared__ unsigned int spack[P_ / 64];   // 1440
    const int b    = blockIdx.y;
    const int tid  = threadIdx.x;
    const int CPIX = P_ / 64;                 // 1440
    const int p0   = blockIdx.x * CPIX;
    const int t    = p0 / HW_;
    const int hw0  = p0 - t * HW_;

    // Phase 1: pack 12 masks/pixel into one uint32
    const int* g0 = gt + (((size_t)b * N_) * T_ + t) * HW_ + hw0;
    for (int k = tid; k < CPIX; k += 512) {
        unsigned w = 0u;
#pragma unroll
        for (int n = 0; n < N_; n++)
            w |= ((unsigned)g0[(size_t)n * (T_ * HW_) + k]) << n;
        spack[k] = w;
        d_pack[(size_t)b * P_ + p0 + k] = w;
    }
    __syncthreads();

    // Phase 2: accumulate (warp w = embed dim e)
    const int e    = tid >> 5;
    const int lane = tid & 31;
    const float* f = (t == 0 ? mf1 : mf2) + ((size_t)b * E_ + e) * HW_ + hw0;

    float s1[N_], s2[N_];
    int   c[N_];
#pragma unroll
    for (int n = 0; n < N_; n++) { s1[n] = 0.f; s2[n] = 0.f; c[n] = 0; }

    for (int k = lane; k < CPIX; k += 32) {
        float x  = f[k];
        float x2 = x * x;
        unsigned pw = spack[k];
#pragma unroll
        for (int n = 0; n < N_; n++) {
            if ((pw >> n) & 1u) { s1[n] += x; s2[n] += x2; c[n]++; }
        }
    }

#pragma unroll
    for (int n = 0; n < N_; n++) {
        float a  = s1[n];
        float bb = s2[n];
        for (int off = 16; off; off >>= 1) {
            a  += __shfl_down_sync(0xffffffffu, a,  off);
            bb += __shfl_down_sync(0xffffffffu, bb, off);
        }
        if (lane == 0) {
            atomicAdd(&d_S1[((size_t)b * N_ + n) * E_ + e], a);
            atomicAdd(&d_S2[((size_t)b * N_ + n) * E_ + e], bb);
        }
    }
    if (e == 0) {
#pragma unroll
        for (int n = 0; n < N_; n++) {
            int cc = c[n];
            for (int off = 16; off; off >>= 1)
                cc += __shfl_down_sync(0xffffffffu, cc, off);
            if (lane == 0) atomicAdd(&d_cnt[b * N_ + n], (unsigned)cc);
        }
    }

    // Fused finalize (last block)
    __threadfence();
    __shared__ bool isLast;
    if (tid == 0) isLast = (atomicAdd(&d_tick1, 1u) == (unsigned)(64 * B_ - 1));
    __syncthreads();
    if (isLast && tid < BN_ * E_) {
        int inst   = tid / E_;
        double cnt = (double)d_cnt[inst];
        double s1v = (double)d_S1[tid];
        double s2v = (double)d_S2[tid];
        double mean = s1v / cnt;
        double var  = (s2v - s1v * s1v / cnt) / (cnt - 1.0);
        d_mean[tid] = (float)mean;
        d_nhv[tid]  = (float)(-0.5 * var);
    }
}

// ---------------------------------------------------------------------------
// Kernel 2: per-pixel distance -> error -> histogram (warp-aggregated atomics)
// grid 720, block 256. One thread = one pixel (covers both batches).
// Warp-uniform fast path: if ALL lanes have d <= -9.71 then every bin is
// exactly 0 (mv=0) or NBINS-1 (mv=1) at this quantization (2*e^-9.71*8192 =
// 16383.01), so the whole warp skips MUFU and needs at most 2 atomics.
// ---------------------------------------------------------------------------
__global__ void __launch_bounds__(256) k_hist(const float* __restrict__ mf1,
                                              const float* __restrict__ mf2) {
    __shared__ float sm_mean[NE_];
    __shared__ float sm_nhv [NE_];
    const int tid = threadIdx.x;
    const int b   = (blockIdx.x * 256) / P_;         // uniform in block (P_ % 256 == 0)
    if (tid < NE_) {
        sm_mean[tid] = d_mean[b * NE_ + tid];
        sm_nhv [tid] = d_nhv [b * NE_ + tid];
    }
    __syncthreads();

    const int pp = blockIdx.x * 256 + tid;           // < B_*P_ exactly
    const int p  = pp - b * P_;
    const int t  = p / HW_;
    const int hw = p - t * HW_;
    const int lane = tid & 31;

    const float* f = (t == 0 ? mf1 : mf2) + (size_t)b * E_ * HW_ + hw;
    float x[E_];
#pragma unroll
    for (int e = 0; e < E_; e++) x[e] = f[(size_t)e * HW_];

    const unsigned pw = d_pack[pp];

#pragma unroll
    for (int n = 0; n < N_; n++) {
        float d = 0.f;
#pragma unroll
        for (int e = 0; e < E_; e++) {
            float diff = x[e] - sm_mean[n * E_ + e];
            d = fmaf(diff * diff, sm_nhv[n * E_ + e], d);  // d = -0.5 * sum
        }
        const unsigned mv = (pw >> n) & 1u;
        const int slotbase = (b * N_ + n) << 1;

        const unsigned fastmask = __ballot_sync(0xffffffffu, d <= -9.71f);
        if (fastmask == 0xffffffffu) {
            // whole warp saturated: bins are exactly 0 (mv=0) / NBINS-1 (mv=1)
            const unsigned mvmask = __ballot_sync(0xffffffffu, mv != 0u);
            if (lane == 0) {
                const int npos = __popc(mvmask);
                if (npos)
                    atomicAdd(&d_hist[(size_t)(slotbase | 1) * NBINS + (NBINS - 1)],
                              (unsigned)npos);
                if (npos < 32)
                    atomicAdd(&d_hist[(size_t)slotbase * NBINS + 0],
                              (unsigned)(32 - npos));
            }
        } else {
            float q   = __expf(d);                   // in (0, 1]
            float err = mv ? fmaf(-2.0f, q, 2.0f) : (2.0f * q);
            int bin   = (int)(err * BIN_SCALE);
            bin       = bin < (NBINS - 1) ? bin : (NBINS - 1);

            // warp-aggregate identical (mv, bin) pairs -> one atomic per group
            unsigned key   = (mv << 14) | (unsigned)bin;
            unsigned peers = __match_any_sync(0xffffffffu, key);
            if (lane == __ffs(peers) - 1) {
                atomicAdd(&d_hist[(size_t)(slotbase | (int)mv) * NBINS + bin],
                          (unsigned)__popc(peers));
            }
        }
    }
}

// ---------------------------------------------------------------------------
// Kernel 3: histogram scan + Lovasz via exact int64 rational + fp32 divide.
// One block per instance; 1024 threads x 16 bins.  Also zeroes the histogram
// bins it read and (last block) resets all accumulators + writes the output.
// ---------------------------------------------------------------------------
__global__ void __launch_bounds__(1024) k_loss(float* __restrict__ out) {
    const int inst = blockIdx.x;
    const int tid  = threadIdx.x;
    const int lane = tid & 31;
    const int wid  = tid >> 5;
    const size_t baseN = ((size_t)(inst * 2)     * NBINS) + (size_t)tid * BPT;
    const size_t baseP = ((size_t)(inst * 2 + 1) * NBINS) + (size_t)tid * BPT;

    unsigned cntP[BPT], cntN[BPT];
    const uint4 z4 = make_uint4(0u, 0u, 0u, 0u);
#pragma unroll
    for (int j = 0; j < BPT; j += 4) {
        uint4 vp = *reinterpret_cast<const uint4*>(&d_hist[baseP + j]);
        uint4 vn = *reinterpret_cast<const uint4*>(&d_hist[baseN + j]);
        cntP[j] = vp.x; cntP[j+1] = vp.y; cntP[j+2] = vp.z; cntP[j+3] = vp.w;
        cntN[j] = vn.x; cntN[j+1] = vn.y; cntN[j+2] = vn.z; cntN[j+3] = vn.w;
        *reinterpret_cast<uint4*>(&d_hist[baseP + j]) = z4;   // self-clean
        *reinterpret_cast<uint4*>(&d_hist[baseN + j]) = z4;
    }
    unsigned tp = 0, tn = 0;
#pragma unroll
    for (int j = 0; j < BPT; j++) { tp += cntP[j]; tn += cntN[j]; }

    // block-wide exclusive scan: warp shuffle scan + cross-warp scan
    __shared__ unsigned swp[32], swn[32];
    unsigned ip = tp, inn = tn;
#pragma unroll
    for (int o = 1; o < 32; o <<= 1) {
        unsigned a = __shfl_up_sync(0xffffffffu, ip,  o);
        unsigned c = __shfl_up_sync(0xffffffffu, inn, o);
        if (lane >= o) { ip += a; inn += c; }
    }
    if (lane == 31) { swp[wid] = ip; swn[wid] = inn; }
    __syncthreads();
    if (wid == 0) {
        unsigned op = swp[lane], on = swn[lane];
        unsigned a = op, c = on;
#pragma unroll
        for (int o = 1; o < 32; o <<= 1) {
            unsigned xa = __shfl_up_sync(0xffffffffu, a, o);
            unsigned xc = __shfl_up_sync(0xffffffffu, c, o);
            if (lane >= o) { a += xa; c += xc; }
        }
        swp[lane] = a - op;          // exclusive warp-total prefix
        swn[lane] = c - on;
    }
    __syncthreads();
    const unsigned runP0 = swp[wid] + (ip - tp);
    const unsigned runN0 = swn[wid] + (inn - tn);

    const long long gts    = (long long)d_cnt[inst];
    const long long totNeg = (long long)P_ - gts;
    long long cp1 = gts    - (long long)runP0;
    long long cn1 = totNeg - (long long)runN0;

    float acc = 0.f;
#pragma unroll
    for (int j = 0; j < BPT; j++) {
        const unsigned cp = cntP[j], cn = cntN[j];
        if (cp | cn) {
            long long num = gts * (long long)(cp + cn)
                          + (long long)cp * cn1 - cp1 * (long long)cn;
            long long den = (gts + cn1 - (long long)cn) * (gts + cn1);
            float e_rep = ((float)(tid * BPT + j) + 0.5f) * DBINF;
            acc += e_rep * ((float)num / (float)den);
        }
        cp1 -= (long long)cp;
        cn1 -= (long long)cn;
    }

    // block reduce (double)
    __shared__ double dw[32];
    double dacc = (double)acc;
#pragma unroll
    for (int o = 16; o; o >>= 1)
        dacc += __shfl_down_sync(0xffffffffu, dacc, o);
    if (lane == 0) dw[wid] = dacc;
    __syncthreads();
    if (wid == 0) {
        double v = dw[lane];
#pragma unroll
        for (int o = 16; o; o >>= 1)
            v += __shfl_down_sync(0xffffffffu, v, o);
        if (lane == 0) atomicAdd(&d_total, v);
    }

    // last block: write scalar output, then reset all state to zero
    __threadfence();
    __shared__ bool isLast;
    if (tid == 0) isLast = (atomicAdd(&d_tick2, 1u) == (unsigned)(BN_ - 1));
    __syncthreads();
    if (isLast) {
        if (tid == 0) {
            out[0] = (float)(d_total / (double)BN_);
            d_total = 0.0;
            d_tick1 = 0u;
            d_tick2 = 0u;
        }
        if (tid < BN_ * E_) { d_S1[tid] = 0.f; d_S2[tid] = 0.f; }
        if (tid < BN_)      { d_cnt[tid] = 0u; }
    }
}

extern "C" void kernel_launch(void* const* d_in, const int* in_sizes, int n_in,
                              void* d_out, int out_size) {
    const float* mf1 = (const float*)d_in[0];
    const float* mf2 = (const float*)d_in[1];
    const int*   gt  = (const int*)d_in[2];

    k_stats<<<dim3(64, B_), 512>>>(mf1, mf2, gt);
    k_hist<<<(B_ * P_) / 256, 256>>>(mf1, mf2);
    k_loss<<<BN_, 1024>>>((float*)d_out);
}

// round 11
// speedup vs baseline: 1.4485x; 1.0322x over previous
#include <cuda_runtime.h>

// Problem constants
#define B_  2
#define E_  16
#define H_  160
#define W_  288
#define N_  12
#define T_  2
#define HW_ (H_ * W_)           // 46080
#define P_  (T_ * HW_)          // 92160 pixels per instance
#define BN_ (B_ * N_)           // 24 instances
#define NE_ (N_ * E_)           // 192
#define NBINS 16384             // error bins over [0, 2]
#define BIN_SCALE 8192.0f       // NBINS / 2
#define DBINF (2.0f / 16384.0f)
#define NSLOT (BN_ * 2)         // slot = inst*2 + mv
#define BPT 16                  // bins per thread in k_loss (NBINS/1024)
#define CPIX 1536               // pixels per stats chunk (divides HW_; 30/frame)
#define SCH (P_ / CPIX)         // 60 chunks per batch

// Scratch (static __device__ arrays — zero-initialized at load; k_loss's last
// block restores the zero state every call, so no clear kernel is needed).
__device__ unsigned int d_hist[NSLOT * NBINS];      // 3.1 MB
__device__ unsigned int d_pack[B_ * P_];            // packed masks, 737 KB
__device__ float        d_S1[BN_ * E_];
__device__ float        d_S2[BN_ * E_];
__device__ unsigned int d_cnt[BN_];
__device__ float        d_mean[BN_ * E_];
__device__ float        d_nhv [BN_ * E_];           // -0.5 * var
__device__ double       d_total;
__device__ unsigned int d_tick1;
__device__ unsigned int d_tick2;

// ---------------------------------------------------------------------------
// Kernel 1: pack masks + masked sums + (fused) finalize of mean/var.
// grid (60, B_), block 512 (warp w = embed dim e).  CPIX=1536 divides HW_,
// so each chunk lies in one frame t.  Inner loop is float4/uint4 vectorized:
// each lane owns 4 consecutive pixels per iteration -> 4 independent adds
// per accumulator chain step (ILP 4) and 1/4 the load instructions.
// ---------------------------------------------------------------------------
__global__ void __launch_bounds__(512) k_stats(const float* __restrict__ mf1,
                                               const float* __restrict__ mf2,
                                               const int*   __restrict__ gt) {
    __shared__ __align__(16) unsigned int spack[CPIX];
    const int b    = blockIdx.y;
    const int tid  = threadIdx.x;
    const int p0   = blockIdx.x * CPIX;
    const int t    = p0 / HW_;
    const int hw0  = p0 - t * HW_;

    // Phase 1: pack 12 masks/pixel into one uint32
    const int* g0 = gt + (((size_t)b * N_) * T_ + t) * HW_ + hw0;
    for (int k = tid; k < CPIX; k += 512) {
        unsigned w = 0u;
#pragma unroll
        for (int n = 0; n < N_; n++)
            w |= ((unsigned)g0[(size_t)n * (T_ * HW_) + k]) << n;
        spack[k] = w;
        d_pack[(size_t)b * P_ + p0 + k] = w;
    }
    __syncthreads();

    // Phase 2: accumulate (warp w = embed dim e), 4 pixels/lane/iteration
    const int e    = tid >> 5;
    const int lane = tid & 31;
    const float4* f4 = reinterpret_cast<const float4*>(
        (t == 0 ? mf1 : mf2) + ((size_t)b * E_ + e) * HW_ + hw0);
    const uint4* pk4 = reinterpret_cast<const uint4*>(spack);

    float s1[N_], s2[N_];
#pragma unroll
    for (int n = 0; n < N_; n++) { s1[n] = 0.f; s2[n] = 0.f; }

#pragma unroll 4
    for (int i = 0; i < CPIX / 128; i++) {          // 12 iterations
        const float4 xv = f4[lane + 32 * i];
        const uint4  pv = pk4[lane + 32 * i];
        const float  xs[4] = {xv.x, xv.y, xv.z, xv.w};
        const unsigned ps[4] = {pv.x, pv.y, pv.z, pv.w};
#pragma unroll
        for (int j = 0; j < 4; j++) {
            const float x  = xs[j];
            const float x2 = x * x;
            const unsigned pw = ps[j];
#pragma unroll
            for (int n = 0; n < N_; n++) {
                if ((pw >> n) & 1u) { s1[n] += x; s2[n] += x2; }
            }
        }
    }

#pragma unroll
    for (int n = 0; n < N_; n++) {
        float a  = s1[n];
        float bb = s2[n];
        for (int off = 16; off; off >>= 1) {
            a  += __shfl_down_sync(0xffffffffu, a,  off);
            bb += __shfl_down_sync(0xffffffffu, bb, off);
        }
        if (lane == 0) {
            atomicAdd(&d_S1[((size_t)b * N_ + n) * E_ + e], a);
            atomicAdd(&d_S2[((size_t)b * N_ + n) * E_ + e], bb);
        }
    }
    if (e == 0) {                                   // counts: warp 0 only
        int c[N_];
#pragma unroll
        for (int n = 0; n < N_; n++) c[n] = 0;
#pragma unroll 4
        for (int i = 0; i < CPIX / 128; i++) {
            const uint4 pv = pk4[lane + 32 * i];
            const unsigned ps[4] = {pv.x, pv.y, pv.z, pv.w};
#pragma unroll
            for (int j = 0; j < 4; j++) {
#pragma unroll
                for (int n = 0; n < N_; n++) c[n] += (int)((ps[j] >> n) & 1u);
            }
        }
#pragma unroll
        for (int n = 0; n < N_; n++) {
            int cc = c[n];
            for (int off = 16; off; off >>= 1)
                cc += __shfl_down_sync(0xffffffffu, cc, off);
            if (lane == 0) atomicAdd(&d_cnt[b * N_ + n], (unsigned)cc);
        }
    }

    // Fused finalize (last block)
    __threadfence();
    __shared__ bool isLast;
    if (tid == 0) isLast = (atomicAdd(&d_tick1, 1u) == (unsigned)(SCH * B_ - 1));
    __syncthreads();
    if (isLast && tid < BN_ * E_) {
        int inst   = tid / E_;
        double cnt = (double)d_cnt[inst];
        double s1v = (double)d_S1[tid];
        double s2v = (double)d_S2[tid];
        double mean = s1v / cnt;
        double var  = (s2v - s1v * s1v / cnt) / (cnt - 1.0);
        d_mean[tid] = (float)mean;
        d_nhv[tid]  = (float)(-0.5 * var);
    }
}

// ---------------------------------------------------------------------------
// Kernel 2: per-pixel distance -> error -> histogram (warp-aggregated atomics)
// grid 720, block 256. One thread = one pixel (covers both batches).
// Exact R5 body — exp fast-path variants tested and rejected (R6/R9).
// ---------------------------------------------------------------------------
__global__ void __launch_bounds__(256) k_hist(const float* __restrict__ mf1,
                                              const float* __restrict__ mf2) {
    __shared__ float sm_mean[NE_];
    __shared__ float sm_nhv [NE_];
    const int tid = threadIdx.x;
    const int b   = (blockIdx.x * 256) / P_;         // uniform in block (P_ % 256 == 0)
    if (tid < NE_) {
        sm_mean[tid] = d_mean[b * NE_ + tid];
        sm_nhv [tid] = d_nhv [b * NE_ + tid];
    }
    __syncthreads();

    const int pp = blockIdx.x * 256 + tid;           // < B_*P_ exactly
    const int p  = pp - b * P_;
    const int t  = p / HW_;
    const int hw = p - t * HW_;
    const int lane = tid & 31;

    const float* f = (t == 0 ? mf1 : mf2) + (size_t)b * E_ * HW_ + hw;
    float x[E_];
#pragma unroll
    for (int e = 0; e < E_; e++) x[e] = f[(size_t)e * HW_];

    const unsigned pw = d_pack[pp];

#pragma unroll
    for (int n = 0; n < N_; n++) {
        float d = 0.f;
#pragma unroll
        for (int e = 0; e < E_; e++) {
            float diff = x[e] - sm_mean[n * E_ + e];
            d = fmaf(diff * diff, sm_nhv[n * E_ + e], d);  // d = -0.5 * sum
        }
        float q   = __expf(d);                       // in (0, 1]
        unsigned mv = (pw >> n) & 1u;
        float err = mv ? fmaf(-2.0f, q, 2.0f) : (2.0f * q);
        int bin   = (int)(err * BIN_SCALE);
        bin       = bin < (NBINS - 1) ? bin : (NBINS - 1);

        // warp-aggregate identical (mv, bin) pairs -> one atomic per group
        unsigned key   = (mv << 14) | (unsigned)bin;
        unsigned peers = __match_any_sync(0xffffffffu, key);
        if (lane == __ffs(peers) - 1) {
            int slot = ((b * N_ + n) << 1) | (int)mv;
            atomicAdd(&d_hist[(size_t)slot * NBINS + bin],
                      (unsigned)__popc(peers));
        }
    }
}

// ---------------------------------------------------------------------------
// Kernel 3: histogram scan + Lovasz via exact int64 rational + fp32 divide.
// One block per instance; 1024 threads x 16 bins.  Also zeroes the histogram
// bins it read and (last block) resets all accumulators + writes the output.
// ---------------------------------------------------------------------------
__global__ void __launch_bounds__(1024) k_loss(float* __restrict__ out) {
    const int inst = blockIdx.x;
    const int tid  = threadIdx.x;
    const int lane = tid & 31;
    const int wid  = tid >> 5;
    const size_t baseN = ((size_t)(inst * 2)     * NBINS) + (size_t)tid * BPT;
    const size_t baseP = ((size_t)(inst * 2 + 1) * NBINS) + (size_t)tid * BPT;

    unsigned cntP[BPT], cntN[BPT];
    const uint4 z4 = make_uint4(0u, 0u, 0u, 0u);
#pragma unroll
    for (int j = 0; j < BPT; j += 4) {
        uint4 vp = *reinterpret_cast<const uint4*>(&d_hist[baseP + j]);
        uint4 vn = *reinterpret_cast<const uint4*>(&d_hist[baseN + j]);
        cntP[j] = vp.x; cntP[j+1] = vp.y; cntP[j+2] = vp.z; cntP[j+3] = vp.w;
        cntN[j] = vn.x; cntN[j+1] = vn.y; cntN[j+2] = vn.z; cntN[j+3] = vn.w;
        *reinterpret_cast<uint4*>(&d_hist[baseP + j]) = z4;   // self-clean
        *reinterpret_cast<uint4*>(&d_hist[baseN + j]) = z4;
    }
    unsigned tp = 0, tn = 0;
#pragma unroll
    for (int j = 0; j < BPT; j++) { tp += cntP[j]; tn += cntN[j]; }

    // block-wide exclusive scan: warp shuffle scan + cross-warp scan
    __shared__ unsigned swp[32], swn[32];
    unsigned ip = tp, inn = tn;
#pragma unroll
    for (int o = 1; o < 32; o <<= 1) {
        unsigned a = __shfl_up_sync(0xffffffffu, ip,  o);
        unsigned c = __shfl_up_sync(0xffffffffu, inn, o);
        if (lane >= o) { ip += a; inn += c; }
    }
    if (lane == 31) { swp[wid] = ip; swn[wid] = inn; }
    __syncthreads();
    if (wid == 0) {
        unsigned op = swp[lane], on = swn[lane];
        unsigned a = op, c = on;
#pragma unroll
        for (int o = 1; o < 32; o <<= 1) {
            unsigned xa = __shfl_up_sync(0xffffffffu, a, o);
            unsigned xc = __shfl_up_sync(0xffffffffu, c, o);
            if (lane >= o) { a += xa; c += xc; }
        }
        swp[lane] = a - op;          // exclusive warp-total prefix
        swn[lane] = c - on;
    }
    __syncthreads();
    const unsigned runP0 = swp[wid] + (ip - tp);
    const unsigned runN0 = swn[wid] + (inn - tn);

    const long long gts    = (long long)d_cnt[inst];
    const long long totNeg = (long long)P_ - gts;
    long long cp1 = gts    - (long long)runP0;
    long long cn1 = totNeg - (long long)runN0;

    float acc = 0.f;
#pragma unroll
    for (int j = 0; j < BPT; j++) {
        const unsigned cp = cntP[j], cn = cntN[j];
        if (cp | cn) {
            long long num = gts * (long long)(cp + cn)
                          + (long long)cp * cn1 - cp1 * (long long)cn;
            long long den = (gts + cn1 - (long long)cn) * (gts + cn1);
            float e_rep = ((float)(tid * BPT + j) + 0.5f) * DBINF;
            acc += e_rep * ((float)num / (float)den);
        }
        cp1 -= (long long)cp;
        cn1 -= (long long)cn;
    }

    // block reduce (double)
    __shared__ double dw[32];
    double dacc = (double)acc;
#pragma unroll
    for (int o = 16; o; o >>= 1)
        dacc += __shfl_down_sync(0xffffffffu, dacc, o);
    if (lane == 0) dw[wid] = dacc;
    __syncthreads();
    if (wid == 0) {
        double v = dw[lane];
#pragma unroll
        for (int o = 16; o; o >>= 1)
            v += __shfl_down_sync(0xffffffffu, v, o);
        if (lane == 0) atomicAdd(&d_total, v);
    }

    // last block: write scalar output, then reset all state to zero
    __threadfence();
    __shared__ bool isLast;
    if (tid == 0) isLast = (atomicAdd(&d_tick2, 1u) == (unsigned)(BN_ - 1));
    __syncthreads();
    if (isLast) {
        if (tid == 0) {
            out[0] = (float)(d_total / (double)BN_);
            d_total = 0.0;
            d_tick1 = 0u;
            d_tick2 = 0u;
        }
        if (tid < BN_ * E_) { d_S1[tid] = 0.f; d_S2[tid] = 0.f; }
        if (tid < BN_)      { d_cnt[tid] = 0u; }
    }
}

extern "C" void kernel_launch(void* const* d_in, const int* in_sizes, int n_in,
                              void* d_out, int out_size) {
    const float* mf1 = (const float*)d_in[0];
    const float* mf2 = (const float*)d_in[1];
    const int*   gt  = (const int*)d_in[2];

    k_stats<<<dim3(SCH, B_), 512>>>(mf1, mf2, gt);
    k_hist<<<(B_ * P_) / 256, 256>>>(mf1, mf2);
    k_loss<<<BN_, 1024>>>((float*)d_out);
}